// round 1
// baseline (speedup 1.0000x reference)
#include <cuda_runtime.h>

#define LEVELS 18
#define NNODES ((1 << LEVELS) - 1)

// Persisted cell state: only the first 64 columns of c are ever consumed by a
// parent, so scratch is NNODES x 64 floats (67 MB) as a device global (no
// runtime allocation allowed).
__device__ float g_c[(long long)NNODES * 64];

__device__ __forceinline__ float sigf(float z) {
    // 1/(1+e^-z); exp overflow -> inf -> 0, no NaN
    return __fdividef(1.0f, 1.0f + __expf(-z));
}
__device__ __forceinline__ float tanha(float z) {
    // 2*sigmoid(2z)-1; saturates cleanly at +-1 for |z| large
    return __fdividef(2.0f, 1.0f + __expf(-2.0f * z)) - 1.0f;
}

// One block = 32 nodes x 512 gates, K = 192 (= 64 x-cols + 128 h_prev-cols).
// 256 threads, 8x8 register tile each (64 accumulators).
__global__ __launch_bounds__(256, 2)
void lstm_level_kernel(const float* __restrict__ x,
                       const float* __restrict__ Wih,
                       const float* __restrict__ Whh,
                       const float* __restrict__ bih,
                       const float* __restrict__ bhh,
                       float* __restrict__ out,
                       int start, int count, int isLeaf)
{
    __shared__ __align__(16) union SM {
        struct {
            float As[32][196];   // [node][k], padded row (196*4B = 16B-aligned)
            float Wc[8][512];    // [k-chunk][gate]
        } p;
        float gates[16][512];    // overlay for elementwise phase (half-tile)
    } sm;

    const int t = threadIdx.x;
    const int tileBase = blockIdx.x * 32;

    // ---- Phase 1: assemble A = [x | h_left[:64] | h_right[:64]] in smem ----
    // 32 nodes * 192 floats = 1536 float4, 6 per thread.
    #pragma unroll
    for (int i = 0; i < 6; ++i) {
        int q    = t + i * 256;
        int node = q / 48;          // 48 float4 per node row
        int c4   = q - node * 48;
        int col  = c4 * 4;
        float4 v = make_float4(0.f, 0.f, 0.f, 0.f);
        int nodeIdx = tileBase + node;
        if (nodeIdx < count) {
            int gnode = start + nodeIdx;
            if (col < 64) {
                v = *reinterpret_cast<const float4*>(x + (long long)gnode * 64 + col);
            } else if (!isLeaf) {
                int child = (col < 128) ? (2 * gnode + 1) : (2 * gnode + 2);
                int cc    = (col < 128) ? (col - 64) : (col - 128);
                v = *reinterpret_cast<const float4*>(out + (long long)child * 128 + cc);
            }
        }
        *reinterpret_cast<float4*>(&sm.p.As[node][col]) = v;
    }

    // ---- Phase 2: GEMM (K streamed in 24 chunks of 8) ----
    const int tx = t & 63;          // gate group: gates [tx*8, tx*8+8)
    const int ty = t >> 6;          // node group: nodes [ty*8, ty*8+8)
    const int gBase = tx * 8;
    const int nBase = ty * 8;

    float acc[8][8];
    {
        float bsum[8];
        #pragma unroll
        for (int gi = 0; gi < 8; ++gi)
            bsum[gi] = bih[gBase + gi] + bhh[gBase + gi];
        #pragma unroll
        for (int n = 0; n < 8; ++n)
            #pragma unroll
            for (int gi = 0; gi < 8; ++gi)
                acc[n][gi] = bsum[gi];
    }

    for (int kc = 0; kc < 24; ++kc) {
        const int k0 = kc * 8;
        __syncthreads();  // previous chunk's readers done before Wc overwrite
        // Load W chunk: 512 gates x 8 k (chunks never straddle the 64-col
        // W_ih/W_hh boundary since 8 | 64). 1024 float4, 4 per thread.
        #pragma unroll
        for (int i = 0; i < 4; ++i) {
            int q  = t + i * 256;
            int g  = q >> 1;
            int kp = (q & 1) * 4;
            int c  = k0 + kp;
            float4 v;
            if (c < 64) v = *reinterpret_cast<const float4*>(Wih + g * 64 + c);
            else        v = *reinterpret_cast<const float4*>(Whh + g * 128 + (c - 64));
            sm.p.Wc[kp + 0][g] = v.x;
            sm.p.Wc[kp + 1][g] = v.y;
            sm.p.Wc[kp + 2][g] = v.z;
            sm.p.Wc[kp + 3][g] = v.w;
        }
        __syncthreads();
        #pragma unroll
        for (int kk = 0; kk < 8; ++kk) {
            float4 w0 = *reinterpret_cast<const float4*>(&sm.p.Wc[kk][gBase]);
            float4 w1 = *reinterpret_cast<const float4*>(&sm.p.Wc[kk][gBase + 4]);
            float a[8];
            #pragma unroll
            for (int n = 0; n < 8; ++n) a[n] = sm.p.As[nBase + n][k0 + kk];
            #pragma unroll
            for (int n = 0; n < 8; ++n) {
                acc[n][0] += a[n] * w0.x;
                acc[n][1] += a[n] * w0.y;
                acc[n][2] += a[n] * w0.z;
                acc[n][3] += a[n] * w0.w;
                acc[n][4] += a[n] * w1.x;
                acc[n][5] += a[n] * w1.y;
                acc[n][6] += a[n] * w1.z;
                acc[n][7] += a[n] * w1.w;
            }
        }
    }

    // ---- Phase 3: fused LSTM elementwise, two halves of 16 nodes ----
    #pragma unroll
    for (int half = 0; half < 2; ++half) {
        __syncthreads();  // region (As/Wc or previous half's gates) now dead
        if ((ty >> 1) == half) {
            int nLocBase = nBase - half * 16;
            #pragma unroll
            for (int n = 0; n < 8; ++n) {
                #pragma unroll
                for (int gi = 0; gi < 8; gi += 4) {
                    float4 v = make_float4(acc[n][gi], acc[n][gi + 1],
                                           acc[n][gi + 2], acc[n][gi + 3]);
                    *reinterpret_cast<float4*>(&sm.gates[nLocBase + n][gBase + gi]) = v;
                }
            }
        }
        __syncthreads();  // gates visible to all
        // 16 nodes x 128 hidden = 2048 outputs, 8 per thread, hu-coalesced
        #pragma unroll
        for (int r = 0; r < 8; ++r) {
            int o    = r * 256 + t;
            int nLoc = o >> 7;
            int hu   = o & 127;
            int nodeIdx = tileBase + half * 16 + nLoc;
            if (nodeIdx < count) {
                int gnode = start + nodeIdx;
                float gv_i = sm.gates[nLoc][hu];
                float gv_f = sm.gates[nLoc][hu + 128];
                float gv_g = sm.gates[nLoc][hu + 256];
                float gv_o = sm.gates[nLoc][hu + 384];
                float cp = 0.f;
                if (!isLeaf) {
                    int child = (hu < 64) ? (2 * gnode + 1) : (2 * gnode + 2);
                    int cc    = (hu < 64) ? hu : (hu - 64);
                    cp = g_c[(long long)child * 64 + cc];
                }
                float c = sigf(gv_f) * cp + sigf(gv_i) * tanha(gv_g);
                float h = sigf(gv_o) * tanha(c);
                out[(long long)gnode * 128 + hu] = h;
                if (hu < 64) g_c[(long long)gnode * 64 + hu] = c;
            }
        }
    }
}

extern "C" void kernel_launch(void* const* d_in, const int* in_sizes, int n_in,
                              void* d_out, int out_size)
{
    const float* x   = (const float*)d_in[0];   // [262143, 64]
    const float* Wih = (const float*)d_in[1];   // [512, 64]
    const float* Whh = (const float*)d_in[2];   // [512, 128]
    const float* bih = (const float*)d_in[3];   // [512]
    const float* bhh = (const float*)d_in[4];   // [512]
    float* out = (float*)d_out;                 // [262143, 128]

    for (int lvl = LEVELS - 1; lvl >= 0; --lvl) {
        int start  = (1 << lvl) - 1;
        int count  = 1 << lvl;
        int blocks = (count + 31) / 32;
        lstm_level_kernel<<<blocks, 256>>>(x, Wih, Whh, bih, bhh, out,
                                           start, count, lvl == LEVELS - 1);
    }
}

// round 3
// speedup vs baseline: 1.6828x; 1.6828x over previous
#include <cuda_runtime.h>
#include <cuda_bf16.h>
#include <cstdint>

#define LEVELS 18
#define NNODES ((1 << LEVELS) - 1)

// Persisted state + preconverted weights (device globals; no runtime alloc).
__device__ float         g_c   [(size_t)NNODES * 64];  // cell state, cols 0..63 only
__device__ __nv_bfloat16 g_hh  [(size_t)NNODES * 64];  // h bf16 hi, cols 0..63
__device__ __nv_bfloat16 g_hl  [(size_t)NNODES * 64];  // h bf16 lo
__device__ __nv_bfloat16 g_Whi [512 * 192];            // [gate][k] concat(Wih,Whh) hi
__device__ __nv_bfloat16 g_Wlo [512 * 192];            // lo
__device__ float         g_bsum[512];

// ------------------------------------------------------------------ helpers
__device__ __forceinline__ uint32_t smem_u32(const void* p) {
    uint32_t a;
    asm("{ .reg .u64 t; cvta.to.shared.u64 t, %1; cvt.u32.u64 %0, t; }"
        : "=r"(a) : "l"(p));
    return a;
}
__device__ __forceinline__ void ldsm_x4(uint32_t* r, uint32_t addr) {
    asm volatile("ldmatrix.sync.aligned.m8n8.x4.shared.b16 {%0,%1,%2,%3}, [%4];"
                 : "=r"(r[0]), "=r"(r[1]), "=r"(r[2]), "=r"(r[3]) : "r"(addr));
}
__device__ __forceinline__ void ldsm_x2(uint32_t* r, uint32_t addr) {
    asm volatile("ldmatrix.sync.aligned.m8n8.x2.shared.b16 {%0,%1}, [%2];"
                 : "=r"(r[0]), "=r"(r[1]) : "r"(addr));
}
__device__ __forceinline__ void mma_bf16(float* d, const uint32_t* a, const uint32_t* b) {
    asm volatile("mma.sync.aligned.m16n8k16.row.col.f32.bf16.bf16.f32 "
                 "{%0,%1,%2,%3}, {%4,%5,%6,%7}, {%8,%9}, {%0,%1,%2,%3};"
                 : "+f"(d[0]), "+f"(d[1]), "+f"(d[2]), "+f"(d[3])
                 : "r"(a[0]), "r"(a[1]), "r"(a[2]), "r"(a[3]), "r"(b[0]), "r"(b[1]));
}
__device__ __forceinline__ void split2(float v, __nv_bfloat16& hi, __nv_bfloat16& lo) {
    hi = __float2bfloat16(v);
    lo = __float2bfloat16(v - __bfloat162float(hi));
}
__device__ __forceinline__ float sigf(float z) {
    return __fdividef(1.0f, 1.0f + __expf(-z));
}
__device__ __forceinline__ float tanha(float z) {
    return __fdividef(2.0f, 1.0f + __expf(-2.0f * z)) - 1.0f;
}

// ---------------------------------------------------------------- SMEM plan
// Row stride 400B (192 halves padded to 200): 400 = 25*16, rows hit distinct
// bank quads (4r mod 32) -> conflict-free ldmatrix.
#define RS 400
#define OFF_BIAS 0
#define OFF_AHI  2048
#define OFF_ALO  (OFF_AHI + 128 * RS)   // 53248
#define OFF_BHI  (OFF_ALO + 128 * RS)   // 104448
#define OFF_BLO  (OFF_BHI + 128 * RS)   // 155648
#define SMEM_TC  (OFF_BLO + 128 * RS)   // 206848

// ---------------------------------------------------------------- prep
__global__ void prep_kernel(const float* __restrict__ Wih,
                            const float* __restrict__ Whh,
                            const float* __restrict__ bih,
                            const float* __restrict__ bhh)
{
    int idx = blockIdx.x * blockDim.x + threadIdx.x;
    if (idx < 512) g_bsum[idx] = bih[idx] + bhh[idx];
    for (int p = idx; p < 512 * 192; p += gridDim.x * blockDim.x) {
        int g = p / 192, k = p - g * 192;
        float v = (k < 64) ? Wih[g * 64 + k] : Whh[g * 128 + (k - 64)];
        __nv_bfloat16 hi, lo;
        split2(v, hi, lo);
        g_Whi[p] = hi;
        g_Wlo[p] = lo;
    }
}

// =====================================================================
// Tensor-core level kernel (HMMA mma.sync): CTA = 128 nodes x 512 gates.
// Gate chunk nc covers columns {t*128 + nc*32 + hu32 : t in 0..3, hu32 in 0..31}
// i.e. all four gate types for hidden units [nc*32, nc*32+32).
// =====================================================================
__global__ __launch_bounds__(256, 1)
void lstm_tc_kernel(const float* __restrict__ x,
                    float* __restrict__ out,
                    int start, int isLeaf)
{
    extern __shared__ __align__(16) char smem[];
    const uint32_t sb = smem_u32(smem);
    const int tid = threadIdx.x;
    const int wid = tid >> 5;
    const int lane = tid & 31;
    const int tileBase = blockIdx.x * 128;

    float* bs = (float*)(smem + OFF_BIAS);
    for (int i = tid; i < 512; i += 256) bs[i] = g_bsum[i];

    // ---- A assembly: [128 rows][192 k] hi/lo, stride RS ----
    // x part: k 0..63 (convert fp32 -> hi/lo pairs)
    for (int p = tid; p < 4096; p += 256) {
        int row = p >> 5;
        int kp  = (p & 31) * 2;
        int gnode = start + tileBase + row;
        float2 xv = *(const float2*)(x + (size_t)gnode * 64 + kp);
        __nv_bfloat16 h0, l0, h1, l1;
        split2(xv.x, h0, l0);
        split2(xv.y, h1, l1);
        __nv_bfloat162 hp = {h0, h1}, lp = {l0, l1};
        *(uint32_t*)(smem + OFF_AHI + row * RS + kp * 2) = *(uint32_t*)&hp;
        *(uint32_t*)(smem + OFF_ALO + row * RS + kp * 2) = *(uint32_t*)&lp;
    }
    // h part: k 64..191 (copy bf16 scratch rows; left child then right child)
    for (int p = tid; p < 2048; p += 256) {
        int row = p >> 4;
        int u   = p & 15;                 // 0..7 left, 8..15 right
        uint4 vh = make_uint4(0, 0, 0, 0), vl = make_uint4(0, 0, 0, 0);
        if (!isLeaf) {
            int gnode = start + tileBase + row;
            int child = (u < 8) ? (2 * gnode + 1) : (2 * gnode + 2);
            int uu = u & 7;
            vh = *(const uint4*)(g_hh + (size_t)child * 64 + uu * 8);
            vl = *(const uint4*)(g_hl + (size_t)child * 64 + uu * 8);
        }
        *(uint4*)(smem + OFF_AHI + row * RS + 128 + u * 16) = vh;
        *(uint4*)(smem + OFF_ALO + row * RS + 128 + u * 16) = vl;
    }

    // per-lane ldmatrix address bases
    const uint32_t aRow = sb + (uint32_t)((wid * 16 + (lane & 15)) * RS + ((lane >> 4) << 4));
    const uint32_t bRow = sb + (uint32_t)((lane & 7) * RS + (((lane >> 3) & 1) << 4));
    const int r0   = wid * 16 + (lane >> 2);
    const int huL0 = (lane & 3) * 2;

    for (int nc = 0; nc < 4; ++nc) {
        __syncthreads();   // all warps done reading previous B chunk (and A ready)
        // ---- load B chunk: 128 rows, row rr -> gate (rr>>5)*128 + nc*32 + (rr&31)
        for (int p = tid; p < 3072; p += 256) {
            int rr = p / 24, u = p - rr * 24;
            int gate = ((rr >> 5) << 7) + (nc << 5) + (rr & 31);
            *(uint4*)(smem + OFF_BHI + rr * RS + u * 16) =
                *(const uint4*)(g_Whi + (size_t)gate * 192 + u * 8);
            *(uint4*)(smem + OFF_BLO + rr * RS + u * 16) =
                *(const uint4*)(g_Wlo + (size_t)gate * 192 + u * 8);
        }
        __syncthreads();

        // ---- MMA: 3 terms x 12 k-steps x 16 n-tiles
        float acc[16][4];
        #pragma unroll
        for (int j = 0; j < 16; ++j)
            #pragma unroll
            for (int c = 0; c < 4; ++c) acc[j][c] = 0.f;

        #pragma unroll
        for (int term = 0; term < 3; ++term) {
            const uint32_t Ab = aRow + (uint32_t)((term == 1) ? OFF_ALO : OFF_AHI);
            const uint32_t Bb = bRow + (uint32_t)((term == 2) ? OFF_BLO : OFF_BHI);
            for (int ks = 0; ks < 12; ++ks) {
                uint32_t a[4];
                ldsm_x4(a, Ab + ks * 32);
                #pragma unroll
                for (int j = 0; j < 16; ++j) {
                    uint32_t b[2];
                    ldsm_x2(b, Bb + j * (8 * RS) + ks * 32);
                    mma_bf16(acc[j], a, b);
                }
            }
        }

        // ---- fused elementwise epilogue (register-local gates) ----
        #pragma unroll
        for (int rh = 0; rh < 2; ++rh) {
            const int row = r0 + 8 * rh;
            const int gnode = start + tileBase + row;
            #pragma unroll
            for (int j0 = 0; j0 < 4; ++j0) {
                const int hu = (nc << 5) + (j0 << 3) + huL0;   // even, pair {hu, hu+1}
                float2 cp = make_float2(0.f, 0.f);
                if (!isLeaf) {
                    int child = (hu < 64) ? (2 * gnode + 1) : (2 * gnode + 2);
                    cp = *(const float2*)(g_c + (size_t)child * 64 + (hu & 63));
                }
                float gi0 = acc[j0     ][2 * rh] + bs[hu];
                float gi1 = acc[j0     ][2 * rh + 1] + bs[hu + 1];
                float gf0 = acc[j0 + 4 ][2 * rh] + bs[128 + hu];
                float gf1 = acc[j0 + 4 ][2 * rh + 1] + bs[128 + hu + 1];
                float gg0 = acc[j0 + 8 ][2 * rh] + bs[256 + hu];
                float gg1 = acc[j0 + 8 ][2 * rh + 1] + bs[256 + hu + 1];
                float go0 = acc[j0 + 12][2 * rh] + bs[384 + hu];
                float go1 = acc[j0 + 12][2 * rh + 1] + bs[384 + hu + 1];
                float c0 = sigf(gf0) * cp.x + sigf(gi0) * tanha(gg0);
                float c1 = sigf(gf1) * cp.y + sigf(gi1) * tanha(gg1);
                float h0 = sigf(go0) * tanha(c0);
                float h1 = sigf(go1) * tanha(c1);
                *(float2*)(out + (size_t)gnode * 128 + hu) = make_float2(h0, h1);
                if (hu < 64) {
                    *(float2*)(g_c + (size_t)gnode * 64 + hu) = make_float2(c0, c1);
                    __nv_bfloat16 hh0, hl0, hh1, hl1;
                    split2(h0, hh0, hl0);
                    split2(h1, hh1, hl1);
                    __nv_bfloat162 hp = {hh0, hh1}, lp = {hl0, hl1};
                    *(uint32_t*)(g_hh + (size_t)gnode * 64 + hu) = *(uint32_t*)&hp;
                    *(uint32_t*)(g_hl + (size_t)gnode * 64 + hu) = *(uint32_t*)&lp;
                }
            }
        }
    }
}

// =====================================================================
// Small-level SIMT kernel: 8 nodes per 256-thread block.
// =====================================================================
__global__ __launch_bounds__(256, 4)
void lstm_small_kernel(const float* __restrict__ x,
                       const float* __restrict__ Wih,
                       const float* __restrict__ Whh,
                       const float* __restrict__ bih,
                       const float* __restrict__ bhh,
                       float* __restrict__ out,
                       int start, int count, int isLeaf)
{
    __shared__ __align__(16) float As[8][196];
    __shared__ __align__(16) float Cs[8][128];
    __shared__ float bsm[512];

    const int t = threadIdx.x;
    const int tileBase = blockIdx.x * 8;

    for (int i = t; i < 512; i += 256) bsm[i] = bih[i] + bhh[i];

    for (int q = t; q < 384; q += 256) {
        int node = q / 48, c4 = q - node * 48, col = c4 * 4;
        float4 v = make_float4(0.f, 0.f, 0.f, 0.f);
        int nodeIdx = tileBase + node;
        if (nodeIdx < count) {
            int gnode = start + nodeIdx;
            if (col < 64) {
                v = *(const float4*)(x + (size_t)gnode * 64 + col);
            } else if (!isLeaf) {
                int child = (col < 128) ? (2 * gnode + 1) : (2 * gnode + 2);
                int cc    = (col < 128) ? (col - 64) : (col - 128);
                v = *(const float4*)(out + (size_t)child * 128 + cc);
            }
        }
        *(float4*)&As[node][col] = v;
    }
    {
        int node = t / 32, col = (t & 31) * 4;
        float4 v = make_float4(0.f, 0.f, 0.f, 0.f);
        int nodeIdx = tileBase + node;
        if (nodeIdx < count && !isLeaf) {
            int gnode = start + nodeIdx;
            int child = (col < 64) ? (2 * gnode + 1) : (2 * gnode + 2);
            int cc    = (col < 64) ? col : (col - 64);
            v = *(const float4*)&g_c[(size_t)child * 64 + cc];
        }
        *(float4*)&Cs[node][col] = v;
    }
    __syncthreads();

    const int hu = t & 127;
    const int np = t >> 7;
    float acc[4][4];
    #pragma unroll
    for (int n = 0; n < 4; ++n)
        #pragma unroll
        for (int g = 0; g < 4; ++g)
            acc[n][g] = bsm[hu + g * 128];

    for (int kc = 0; kc < 48; ++kc) {
        const int k0 = kc * 4;
        float4 w[4];
        #pragma unroll
        for (int g = 0; g < 4; ++g) {
            int grow = hu + g * 128;
            w[g] = (k0 < 64)
                 ? *(const float4*)(Wih + (size_t)grow * 64 + k0)
                 : *(const float4*)(Whh + (size_t)grow * 128 + (k0 - 64));
        }
        #pragma unroll
        for (int n = 0; n < 4; ++n) {
            float4 a = *(const float4*)&As[np + 2 * n][k0];
            #pragma unroll
            for (int g = 0; g < 4; ++g)
                acc[n][g] += a.x * w[g].x + a.y * w[g].y + a.z * w[g].z + a.w * w[g].w;
        }
    }

    #pragma unroll
    for (int n = 0; n < 4; ++n) {
        int nn = np + 2 * n;
        int nodeIdx = tileBase + nn;
        if (nodeIdx < count) {
            int gnode = start + nodeIdx;
            float cp = Cs[nn][hu];
            float c = sigf(acc[n][1]) * cp + sigf(acc[n][0]) * tanha(acc[n][2]);
            float h = sigf(acc[n][3]) * tanha(c);
            out[(size_t)gnode * 128 + hu] = h;
            if (hu < 64) g_c[(size_t)gnode * 64 + hu] = c;
        }
    }
}

extern "C" void kernel_launch(void* const* d_in, const int* in_sizes, int n_in,
                              void* d_out, int out_size)
{
    const float* x   = (const float*)d_in[0];   // [262143, 64]
    const float* Wih = (const float*)d_in[1];   // [512, 64]
    const float* Whh = (const float*)d_in[2];   // [512, 128]
    const float* bih = (const float*)d_in[3];   // [512]
    const float* bhh = (const float*)d_in[4];   // [512]
    float* out = (float*)d_out;                 // [262143, 128]

    static bool attr_done = false;
    if (!attr_done) {
        cudaFuncSetAttribute(lstm_tc_kernel,
                             cudaFuncAttributeMaxDynamicSharedMemorySize, SMEM_TC);
        attr_done = true;
    }

    prep_kernel<<<96, 256>>>(Wih, Whh, bih, bhh);

    for (int lvl = LEVELS - 1; lvl >= 0; --lvl) {
        int start = (1 << lvl) - 1;
        int count = 1 << lvl;
        int isLeaf = (lvl == LEVELS - 1);
        if (count >= 2048) {
            lstm_tc_kernel<<<count / 128, 256, SMEM_TC>>>(x, out, start, isLeaf);
        } else {
            lstm_small_kernel<<<(count + 7) / 8, 256>>>(
                x, Wih, Whh, bih, bhh, out, start, count, isLeaf);
        }
    }
}

// round 4
// speedup vs baseline: 2.2075x; 1.3118x over previous
#include <cuda_runtime.h>
#include <cuda_bf16.h>
#include <cstdint>

#define LEVELS 18
#define NNODES ((1 << LEVELS) - 1)

// Persisted state + preconverted weights (device globals; no runtime alloc).
__device__ float         g_c   [(size_t)NNODES * 64];  // cell state, cols 0..63 only
__device__ __nv_bfloat16 g_hh  [(size_t)NNODES * 64];  // h bf16 hi, cols 0..63
__device__ __nv_bfloat16 g_hl  [(size_t)NNODES * 64];  // h bf16 lo
__device__ __nv_bfloat16 g_Whi [512 * 192];            // [gate][k] concat(Wih,Whh) hi
__device__ __nv_bfloat16 g_Wlo [512 * 192];            // lo
__device__ float         g_bsum[512];

// ------------------------------------------------------------------ helpers
__device__ __forceinline__ uint32_t smem_u32(const void* p) {
    uint32_t a;
    asm("{ .reg .u64 t; cvta.to.shared.u64 t, %1; cvt.u32.u64 %0, t; }"
        : "=r"(a) : "l"(p));
    return a;
}
__device__ __forceinline__ void ldsm_x4(uint32_t* r, uint32_t addr) {
    asm volatile("ldmatrix.sync.aligned.m8n8.x4.shared.b16 {%0,%1,%2,%3}, [%4];"
                 : "=r"(r[0]), "=r"(r[1]), "=r"(r[2]), "=r"(r[3]) : "r"(addr));
}
__device__ __forceinline__ void ldsm_x2(uint32_t* r, uint32_t addr) {
    asm volatile("ldmatrix.sync.aligned.m8n8.x2.shared.b16 {%0,%1}, [%2];"
                 : "=r"(r[0]), "=r"(r[1]) : "r"(addr));
}
__device__ __forceinline__ void mma_bf16(float* d, const uint32_t* a, const uint32_t* b) {
    asm volatile("mma.sync.aligned.m16n8k16.row.col.f32.bf16.bf16.f32 "
                 "{%0,%1,%2,%3}, {%4,%5,%6,%7}, {%8,%9}, {%0,%1,%2,%3};"
                 : "+f"(d[0]), "+f"(d[1]), "+f"(d[2]), "+f"(d[3])
                 : "r"(a[0]), "r"(a[1]), "r"(a[2]), "r"(a[3]), "r"(b[0]), "r"(b[1]));
}
__device__ __forceinline__ void split2(float v, __nv_bfloat16& hi, __nv_bfloat16& lo) {
    hi = __float2bfloat16(v);
    lo = __float2bfloat16(v - __bfloat162float(hi));
}
__device__ __forceinline__ float sigf(float z) {
    return __fdividef(1.0f, 1.0f + __expf(-z));
}
__device__ __forceinline__ float tanha(float z) {
    return __fdividef(2.0f, 1.0f + __expf(-2.0f * z)) - 1.0f;
}

// ---------------------------------------------------------------- SMEM plan
// Row stride 400B (192 halves padded to 200): rows hit distinct bank quads,
// conflict-free ldmatrix.
#define RS 400
#define OFF_BIAS 0
#define OFF_AHI  2048
#define OFF_ALO  (OFF_AHI + 128 * RS)
#define OFF_BHI  (OFF_ALO + 128 * RS)
#define OFF_BLO  (OFF_BHI + 128 * RS)
#define SMEM_TC  (OFF_BLO + 128 * RS)   // 206848

// ---------------------------------------------------------------- prep
__global__ void prep_kernel(const float* __restrict__ Wih,
                            const float* __restrict__ Whh,
                            const float* __restrict__ bih,
                            const float* __restrict__ bhh)
{
    int idx = blockIdx.x * blockDim.x + threadIdx.x;
    if (idx < 512) g_bsum[idx] = bih[idx] + bhh[idx];
    for (int p = idx; p < 512 * 192; p += gridDim.x * blockDim.x) {
        int g = p / 192, k = p - g * 192;
        float v = (k < 64) ? Wih[g * 64 + k] : Whh[g * 128 + (k - 64)];
        __nv_bfloat16 hi, lo;
        split2(v, hi, lo);
        g_Whi[p] = hi;
        g_Wlo[p] = lo;
    }
}

// =====================================================================
// Tensor-core level kernel (HMMA mma.sync): CTA = 128 nodes x 512 gates.
// 16 warps: warp = (row group 16 nodes) x (half of 128-gate chunk, 8 j-tiles).
// Chunk gate map: tile j -> gate type (j&3), hidden group (j>>2); B row
// rr = 8j+p -> gate ((j&3)<<7) + nc*32 + ((j>>2)<<3) + p. Each warp-half thus
// holds full (i,f,g,o) quads -> register-local LSTM epilogue.
// =====================================================================
__global__ __launch_bounds__(512, 1)
void lstm_tc_kernel(const float* __restrict__ x,
                    float* __restrict__ out,
                    int start, int isLeaf)
{
    extern __shared__ __align__(16) char smem[];
    const uint32_t sb = smem_u32(smem);
    const int tid = threadIdx.x;
    const int wid = tid >> 5;
    const int lane = tid & 31;
    const int rg = wid & 7;        // row group
    const int ch = wid >> 3;       // chunk half (gate j-tiles ch*8..ch*8+7)
    const int tileBase = blockIdx.x * 128;

    float* bs = (float*)(smem + OFF_BIAS);
    if (tid < 512) bs[tid] = g_bsum[tid];

    // ---- A assembly: [128 rows][192 k] hi/lo, stride RS ----
    for (int p = tid; p < 4096; p += 512) {        // x part: k 0..63
        int row = p >> 5;
        int kp  = (p & 31) * 2;
        int gnode = start + tileBase + row;
        float2 xv = *(const float2*)(x + (size_t)gnode * 64 + kp);
        __nv_bfloat16 h0, l0, h1, l1;
        split2(xv.x, h0, l0);
        split2(xv.y, h1, l1);
        __nv_bfloat162 hp = {h0, h1}, lp = {l0, l1};
        *(uint32_t*)(smem + OFF_AHI + row * RS + kp * 2) = *(uint32_t*)&hp;
        *(uint32_t*)(smem + OFF_ALO + row * RS + kp * 2) = *(uint32_t*)&lp;
    }
    for (int p = tid; p < 2048; p += 512) {        // h part: k 64..191
        int row = p >> 4;
        int u   = p & 15;                          // 0..7 left, 8..15 right
        uint4 vh = make_uint4(0, 0, 0, 0), vl = make_uint4(0, 0, 0, 0);
        if (!isLeaf) {
            int gnode = start + tileBase + row;
            int child = (u < 8) ? (2 * gnode + 1) : (2 * gnode + 2);
            int uu = u & 7;
            vh = *(const uint4*)(g_hh + (size_t)child * 64 + uu * 8);
            vl = *(const uint4*)(g_hl + (size_t)child * 64 + uu * 8);
        }
        *(uint4*)(smem + OFF_AHI + row * RS + 128 + u * 16) = vh;
        *(uint4*)(smem + OFF_ALO + row * RS + 128 + u * 16) = vl;
    }

    // per-lane ldmatrix bases
    const uint32_t aHi = sb + OFF_AHI + (uint32_t)((rg * 16 + (lane & 15)) * RS + ((lane >> 4) << 4));
    const uint32_t aLo = aHi + (OFF_ALO - OFF_AHI);
    const uint32_t bHi = sb + OFF_BHI + (uint32_t)(ch * 64 * RS + (lane & 7) * RS + (((lane >> 3) & 1) << 4));
    const uint32_t bLo = bHi + (OFF_BLO - OFF_BHI);
    const int r0   = rg * 16 + (lane >> 2);
    const int huL0 = (lane & 3) * 2;

    for (int nc = 0; nc < 4; ++nc) {
        __syncthreads();   // prior chunk fully consumed (and A visible on nc=0)
        // ---- load B chunk: 128 rows x 24 uint4 per hi/lo
        for (int p = tid; p < 3072; p += 512) {
            int rr = p / 24, u = p - rr * 24;
            int j = rr >> 3, w = rr & 7;
            int gate = ((j & 3) << 7) + (nc << 5) + ((j >> 2) << 3) + w;
            *(uint4*)(smem + OFF_BHI + rr * RS + u * 16) =
                *(const uint4*)(g_Whi + (size_t)gate * 192 + u * 8);
            *(uint4*)(smem + OFF_BLO + rr * RS + u * 16) =
                *(const uint4*)(g_Wlo + (size_t)gate * 192 + u * 8);
        }
        __syncthreads();

        // ---- MMA: 12 k-steps; per step share A/B fragments across 3 terms
        float acc[8][4];
        #pragma unroll
        for (int j = 0; j < 8; ++j)
            #pragma unroll
            for (int c = 0; c < 4; ++c) acc[j][c] = 0.f;

        #pragma unroll
        for (int ks = 0; ks < 12; ++ks) {
            uint32_t ah[4], al[4];
            ldsm_x4(ah, aHi + ks * 32);
            ldsm_x4(al, aLo + ks * 32);
            #pragma unroll
            for (int jj = 0; jj < 8; ++jj) {
                uint32_t bh[2], bl[2];
                ldsm_x2(bh, bHi + jj * (8 * RS) + ks * 32);
                ldsm_x2(bl, bLo + jj * (8 * RS) + ks * 32);
                mma_bf16(acc[jj], ah, bh);
                mma_bf16(acc[jj], al, bh);
                mma_bf16(acc[jj], ah, bl);
            }
        }

        // ---- fused elementwise epilogue (register-local gate quads) ----
        #pragma unroll
        for (int g2 = 0; g2 < 2; ++g2) {
            const int hu = (nc << 5) + ((ch * 2 + g2) << 3) + huL0;  // even pair
            #pragma unroll
            for (int rh = 0; rh < 2; ++rh) {
                const int row = r0 + 8 * rh;
                const int gnode = start + tileBase + row;
                float2 cp = make_float2(0.f, 0.f);
                if (!isLeaf) {
                    int child = (hu < 64) ? (2 * gnode + 1) : (2 * gnode + 2);
                    cp = *(const float2*)(g_c + (size_t)child * 64 + (hu & 63));
                }
                float gi0 = acc[g2 * 4 + 0][2 * rh]     + bs[hu];
                float gi1 = acc[g2 * 4 + 0][2 * rh + 1] + bs[hu + 1];
                float gf0 = acc[g2 * 4 + 1][2 * rh]     + bs[128 + hu];
                float gf1 = acc[g2 * 4 + 1][2 * rh + 1] + bs[128 + hu + 1];
                float gg0 = acc[g2 * 4 + 2][2 * rh]     + bs[256 + hu];
                float gg1 = acc[g2 * 4 + 2][2 * rh + 1] + bs[256 + hu + 1];
                float go0 = acc[g2 * 4 + 3][2 * rh]     + bs[384 + hu];
                float go1 = acc[g2 * 4 + 3][2 * rh + 1] + bs[384 + hu + 1];
                float c0 = sigf(gf0) * cp.x + sigf(gi0) * tanha(gg0);
                float c1 = sigf(gf1) * cp.y + sigf(gi1) * tanha(gg1);
                float h0 = sigf(go0) * tanha(c0);
                float h1 = sigf(go1) * tanha(c1);
                *(float2*)(out + (size_t)gnode * 128 + hu) = make_float2(h0, h1);
                if (hu < 64) {
                    *(float2*)(g_c + (size_t)gnode * 64 + hu) = make_float2(c0, c1);
                    __nv_bfloat16 hh0, hl0, hh1, hl1;
                    split2(h0, hh0, hl0);
                    split2(h1, hh1, hl1);
                    __nv_bfloat162 hp = {hh0, hh1}, lp = {hl0, hl1};
                    *(uint32_t*)(g_hh + (size_t)gnode * 64 + hu) = *(uint32_t*)&hp;
                    *(uint32_t*)(g_hl + (size_t)gnode * 64 + hu) = *(uint32_t*)&lp;
                }
            }
        }
    }
}

// =====================================================================
// Small-level SIMT kernel: 8 nodes per 256-thread block.
// =====================================================================
__global__ __launch_bounds__(256, 4)
void lstm_small_kernel(const float* __restrict__ x,
                       const float* __restrict__ Wih,
                       const float* __restrict__ Whh,
                       const float* __restrict__ bih,
                       const float* __restrict__ bhh,
                       float* __restrict__ out,
                       int start, int count, int isLeaf)
{
    __shared__ __align__(16) float As[8][196];
    __shared__ __align__(16) float Cs[8][128];
    __shared__ float bsm[512];

    const int t = threadIdx.x;
    const int tileBase = blockIdx.x * 8;

    for (int i = t; i < 512; i += 256) bsm[i] = bih[i] + bhh[i];

    for (int q = t; q < 384; q += 256) {
        int node = q / 48, c4 = q - node * 48, col = c4 * 4;
        float4 v = make_float4(0.f, 0.f, 0.f, 0.f);
        int nodeIdx = tileBase + node;
        if (nodeIdx < count) {
            int gnode = start + nodeIdx;
            if (col < 64) {
                v = *(const float4*)(x + (size_t)gnode * 64 + col);
            } else if (!isLeaf) {
                int child = (col < 128) ? (2 * gnode + 1) : (2 * gnode + 2);
                int cc    = (col < 128) ? (col - 64) : (col - 128);
                v = *(const float4*)(out + (size_t)child * 128 + cc);
            }
        }
        *(float4*)&As[node][col] = v;
    }
    {
        int node = t / 32, col = (t & 31) * 4;
        float4 v = make_float4(0.f, 0.f, 0.f, 0.f);
        int nodeIdx = tileBase + node;
        if (nodeIdx < count && !isLeaf) {
            int gnode = start + nodeIdx;
            int child = (col < 64) ? (2 * gnode + 1) : (2 * gnode + 2);
            int cc    = (col < 64) ? col : (col - 64);
            v = *(const float4*)&g_c[(size_t)child * 64 + cc];
        }
        *(float4*)&Cs[node][col] = v;
    }
    __syncthreads();

    const int hu = t & 127;
    const int np = t >> 7;
    float acc[4][4];
    #pragma unroll
    for (int n = 0; n < 4; ++n)
        #pragma unroll
        for (int g = 0; g < 4; ++g)
            acc[n][g] = bsm[hu + g * 128];

    for (int kc = 0; kc < 48; ++kc) {
        const int k0 = kc * 4;
        float4 w[4];
        #pragma unroll
        for (int g = 0; g < 4; ++g) {
            int grow = hu + g * 128;
            w[g] = (k0 < 64)
                 ? *(const float4*)(Wih + (size_t)grow * 64 + k0)
                 : *(const float4*)(Whh + (size_t)grow * 128 + (k0 - 64));
        }
        #pragma unroll
        for (int n = 0; n < 4; ++n) {
            float4 a = *(const float4*)&As[np + 2 * n][k0];
            #pragma unroll
            for (int g = 0; g < 4; ++g)
                acc[n][g] += a.x * w[g].x + a.y * w[g].y + a.z * w[g].z + a.w * w[g].w;
        }
    }

    #pragma unroll
    for (int n = 0; n < 4; ++n) {
        int nn = np + 2 * n;
        int nodeIdx = tileBase + nn;
        if (nodeIdx < count) {
            int gnode = start + nodeIdx;
            float cp = Cs[nn][hu];
            float c = sigf(acc[n][1]) * cp + sigf(acc[n][0]) * tanha(acc[n][2]);
            float h = sigf(acc[n][3]) * tanha(c);
            out[(size_t)gnode * 128 + hu] = h;
            if (hu < 64) g_c[(size_t)gnode * 64 + hu] = c;
        }
    }
}

extern "C" void kernel_launch(void* const* d_in, const int* in_sizes, int n_in,
                              void* d_out, int out_size)
{
    const float* x   = (const float*)d_in[0];   // [262143, 64]
    const float* Wih = (const float*)d_in[1];   // [512, 64]
    const float* Whh = (const float*)d_in[2];   // [512, 128]
    const float* bih = (const float*)d_in[3];   // [512]
    const float* bhh = (const float*)d_in[4];   // [512]
    float* out = (float*)d_out;                 // [262143, 128]

    static bool attr_done = false;
    if (!attr_done) {
        cudaFuncSetAttribute(lstm_tc_kernel,
                             cudaFuncAttributeMaxDynamicSharedMemorySize, SMEM_TC);
        attr_done = true;
    }

    prep_kernel<<<96, 256>>>(Wih, Whh, bih, bhh);

    for (int lvl = LEVELS - 1; lvl >= 0; --lvl) {
        int start = (1 << lvl) - 1;
        int count = 1 << lvl;
        int isLeaf = (lvl == LEVELS - 1);
        if (count >= 2048) {
            lstm_tc_kernel<<<count / 128, 512, SMEM_TC>>>(x, out, start, isLeaf);
        } else {
            lstm_small_kernel<<<(count + 7) / 8, 256>>>(
                x, Wih, Whh, bih, bhh, out, start, count, isLeaf);
        }
    }
}

// round 5
// speedup vs baseline: 2.4306x; 1.1010x over previous
#include <cuda_runtime.h>
#include <cuda_bf16.h>
#include <cstdint>

#define LEVELS 18
#define NNODES ((1 << LEVELS) - 1)

// Persisted state + preconverted weights (device globals; no runtime alloc).
__device__ float         g_c   [(size_t)NNODES * 64];  // cell state, cols 0..63 only
__device__ __nv_bfloat16 g_hh  [(size_t)NNODES * 64];  // h bf16 hi, cols 0..63
__device__ __nv_bfloat16 g_hl  [(size_t)NNODES * 64];  // h bf16 lo
__device__ __nv_bfloat16 g_Whi [512 * 192];            // [gate][k] concat(Wih,Whh) hi
__device__ __nv_bfloat16 g_Wlo [512 * 192];            // lo
__device__ float         g_bsum[512];

// ------------------------------------------------------------------ helpers
__device__ __forceinline__ uint32_t smem_u32(const void* p) {
    uint32_t a;
    asm("{ .reg .u64 t; cvta.to.shared.u64 t, %1; cvt.u32.u64 %0, t; }"
        : "=r"(a) : "l"(p));
    return a;
}
__device__ __forceinline__ void ldsm_x4(uint32_t* r, uint32_t addr) {
    asm volatile("ldmatrix.sync.aligned.m8n8.x4.shared.b16 {%0,%1,%2,%3}, [%4];"
                 : "=r"(r[0]), "=r"(r[1]), "=r"(r[2]), "=r"(r[3]) : "r"(addr));
}
__device__ __forceinline__ void mma_bf16(float* d, const uint32_t* a, const uint32_t* b) {
    asm volatile("mma.sync.aligned.m16n8k16.row.col.f32.bf16.bf16.f32 "
                 "{%0,%1,%2,%3}, {%4,%5,%6,%7}, {%8,%9}, {%0,%1,%2,%3};"
                 : "+f"(d[0]), "+f"(d[1]), "+f"(d[2]), "+f"(d[3])
                 : "r"(a[0]), "r"(a[1]), "r"(a[2]), "r"(a[3]), "r"(b[0]), "r"(b[1]));
}
__device__ __forceinline__ void cp_async16(uint32_t saddr, const void* g) {
    asm volatile("cp.async.ca.shared.global [%0], [%1], 16;"
                 :: "r"(saddr), "l"(g) : "memory");
}
__device__ __forceinline__ void cp_async_commit() {
    asm volatile("cp.async.commit_group;" ::: "memory");
}
__device__ __forceinline__ void cp_async_wait0() {
    asm volatile("cp.async.wait_group 0;" ::: "memory");
}
__device__ __forceinline__ void split2(float v, __nv_bfloat16& hi, __nv_bfloat16& lo) {
    hi = __float2bfloat16(v);
    lo = __float2bfloat16(v - __bfloat162float(hi));
}
__device__ __forceinline__ float sigf(float z) {
    return __fdividef(1.0f, 1.0f + __expf(-z));
}
__device__ __forceinline__ float tanha(float z) {
    return __fdividef(2.0f, 1.0f + __expf(-2.0f * z)) - 1.0f;
}

// ---------------------------------------------------------------- SMEM plan
// Row stride 400B: rows hit distinct bank quads -> conflict-free ldmatrix.
#define RS 400
#define OFF_BIAS 0
#define OFF_AHI  2048
#define OFF_ALO  (OFF_AHI + 64 * RS)    // 27648
#define OFF_BHI  (OFF_ALO + 64 * RS)    // 53248
#define OFF_BLO  (OFF_BHI + 64 * RS)    // 78848
#define SMEM_TC  (OFF_BLO + 64 * RS)    // 104448 -> 2 CTAs/SM

// ---------------------------------------------------------------- prep
__global__ void prep_kernel(const float* __restrict__ Wih,
                            const float* __restrict__ Whh,
                            const float* __restrict__ bih,
                            const float* __restrict__ bhh)
{
    int idx = blockIdx.x * blockDim.x + threadIdx.x;
    if (idx < 512) g_bsum[idx] = bih[idx] + bhh[idx];
    for (int p = idx; p < 512 * 192; p += gridDim.x * blockDim.x) {
        int g = p / 192, k = p - g * 192;
        float v = (k < 64) ? Wih[g * 64 + k] : Whh[g * 128 + (k - 64)];
        __nv_bfloat16 hi, lo;
        split2(v, hi, lo);
        g_Whi[p] = hi;
        g_Wlo[p] = lo;
    }
}

// =====================================================================
// Tensor-core level kernel: CTA = 64 nodes x 512 gates, 8 warps, 2 CTAs/SM.
// 8 gate-chunks of 64. Warp = (row group rg: 16 nodes) x (chunk half ch).
// Chunk tile j (0..7): gate type j&3, hidden group j>>2; warp ch owns
// j = 4ch..4ch+3 = full (i,f,g,o) quad of one hu-group -> register-local
// epilogue. B row rr=8j+p -> gate ((j&3)<<7) + nc*16 + ((j>>2)<<3) + p.
// =====================================================================
__global__ __launch_bounds__(256, 2)
void lstm_tc_kernel(const float* __restrict__ x,
                    float* __restrict__ out,
                    int start, int isLeaf)
{
    extern __shared__ __align__(16) char smem[];
    const uint32_t sb = smem_u32(smem);
    const int tid = threadIdx.x;
    const int lane = tid & 31;
    const int rg = (tid >> 5) & 3;     // row group (16 nodes)
    const int ch = tid >> 7;           // chunk half (j-tiles 4ch..4ch+3)
    const int tileBase = blockIdx.x * 64;

    float* bs = (float*)(smem + OFF_BIAS);
    for (int i = tid; i < 512; i += 256) bs[i] = g_bsum[i];

    // ---- A assembly: [64 rows][192 k] hi/lo, stride RS ----
    for (int p = tid; p < 2048; p += 256) {        // x part: k 0..63 (convert)
        int row = p >> 5;
        int kp  = (p & 31) * 2;
        int gnode = start + tileBase + row;
        float2 xv = *(const float2*)(x + (size_t)gnode * 64 + kp);
        __nv_bfloat16 h0, l0, h1, l1;
        split2(xv.x, h0, l0);
        split2(xv.y, h1, l1);
        __nv_bfloat162 hp = {h0, h1}, lp = {l0, l1};
        *(uint32_t*)(smem + OFF_AHI + row * RS + kp * 2) = *(uint32_t*)&hp;
        *(uint32_t*)(smem + OFF_ALO + row * RS + kp * 2) = *(uint32_t*)&lp;
    }
    if (!isLeaf) {                                  // h part: k 64..191, cp.async
        for (int p = tid; p < 1024; p += 256) {
            int row = p >> 4;
            int u   = p & 15;                       // 0..7 left, 8..15 right
            int gnode = start + tileBase + row;
            int child = (u < 8) ? (2 * gnode + 1) : (2 * gnode + 2);
            int uu = u & 7;
            uint32_t da = sb + (uint32_t)(row * RS + 128 + u * 16);
            cp_async16(da + OFF_AHI, g_hh + (size_t)child * 64 + uu * 8);
            cp_async16(da + OFF_ALO, g_hl + (size_t)child * 64 + uu * 8);
        }
    } else {
        for (int p = tid; p < 1024; p += 256) {
            int row = p >> 4;
            int u   = p & 15;
            uint4 z = make_uint4(0, 0, 0, 0);
            *(uint4*)(smem + OFF_AHI + row * RS + 128 + u * 16) = z;
            *(uint4*)(smem + OFF_ALO + row * RS + 128 + u * 16) = z;
        }
    }
    cp_async_commit();

    // per-lane ldmatrix bases
    const uint32_t aHi = sb + OFF_AHI +
        (uint32_t)((rg * 16 + (lane & 15)) * RS + ((lane >> 4) << 4));
    const uint32_t aLo = aHi + (OFF_ALO - OFF_AHI);
    // B x4 covers 2 k-steps: lanes 0-7/8-15/16-23/24-31 -> k offs 0/16/32/48
    const uint32_t bHi = sb + OFF_BHI +
        (uint32_t)(ch * 32 * RS + (lane & 7) * RS + ((lane >> 3) << 4));
    const uint32_t bLo = bHi + (OFF_BLO - OFF_BHI);
    const int r0   = rg * 16 + (lane >> 2);
    const int huL0 = (lane & 3) * 2;

    for (int nc = 0; nc < 8; ++nc) {
        __syncthreads();   // prior chunk consumed (nc=0: A stores visible)
        // ---- B chunk: 64 rows x 24 uint4, hi+lo, via cp.async
        for (int p = tid; p < 1536; p += 256) {
            int rr = p / 24, u = p - rr * 24;
            int j = rr >> 3, w = rr & 7;
            int gate = ((j & 3) << 7) + (nc << 4) + ((j >> 2) << 3) + w;
            uint32_t da = (uint32_t)(rr * RS + u * 16);
            cp_async16(sb + OFF_BHI + da, g_Whi + (size_t)gate * 192 + u * 8);
            cp_async16(sb + OFF_BLO + da, g_Wlo + (size_t)gate * 192 + u * 8);
        }
        cp_async_commit();
        cp_async_wait0();
        __syncthreads();

        // ---- MMA: 6 double-k-steps; share fragments across the 3 terms
        float acc[4][4];
        #pragma unroll
        for (int j = 0; j < 4; ++j)
            #pragma unroll
            for (int c = 0; c < 4; ++c) acc[j][c] = 0.f;

        #pragma unroll
        for (int dk = 0; dk < 6; ++dk) {
            uint32_t ah0[4], al0[4], ah1[4], al1[4];
            ldsm_x4(ah0, aHi + dk * 64);
            ldsm_x4(al0, aLo + dk * 64);
            ldsm_x4(ah1, aHi + dk * 64 + 32);
            ldsm_x4(al1, aLo + dk * 64 + 32);
            #pragma unroll
            for (int jj = 0; jj < 4; ++jj) {
                uint32_t bh[4], bl[4];
                ldsm_x4(bh, bHi + jj * (8 * RS) + dk * 64);
                ldsm_x4(bl, bLo + jj * (8 * RS) + dk * 64);
                mma_bf16(acc[jj], ah0, bh);
                mma_bf16(acc[jj], al0, bh);
                mma_bf16(acc[jj], ah0, bl);
                mma_bf16(acc[jj], ah1, bh + 2);
                mma_bf16(acc[jj], al1, bh + 2);
                mma_bf16(acc[jj], ah1, bl + 2);
            }
        }

        // ---- fused LSTM epilogue: this warp owns full (i,f,g,o) quad ----
        const int hu = (nc << 4) + (ch << 3) + huL0;   // even pair {hu, hu+1}
        #pragma unroll
        for (int rh = 0; rh < 2; ++rh) {
            const int row = r0 + 8 * rh;
            const int gnode = start + tileBase + row;
            float2 cp = make_float2(0.f, 0.f);
            if (!isLeaf && hu < 64) {
                int child = 2 * gnode + 1;
                cp = *(const float2*)(g_c + (size_t)child * 64 + hu);
            } else if (!isLeaf) {
                int child = 2 * gnode + 2;
                cp = *(const float2*)(g_c + (size_t)child * 64 + (hu - 64));
            }
            float gi0 = acc[0][2 * rh]     + bs[hu];
            float gi1 = acc[0][2 * rh + 1] + bs[hu + 1];
            float gf0 = acc[1][2 * rh]     + bs[128 + hu];
            float gf1 = acc[1][2 * rh + 1] + bs[128 + hu + 1];
            float gg0 = acc[2][2 * rh]     + bs[256 + hu];
            float gg1 = acc[2][2 * rh + 1] + bs[256 + hu + 1];
            float go0 = acc[3][2 * rh]     + bs[384 + hu];
            float go1 = acc[3][2 * rh + 1] + bs[384 + hu + 1];
            float c0 = sigf(gf0) * cp.x + sigf(gi0) * tanha(gg0);
            float c1 = sigf(gf1) * cp.y + sigf(gi1) * tanha(gg1);
            float h0 = sigf(go0) * tanha(c0);
            float h1 = sigf(go1) * tanha(c1);
            *(float2*)(out + (size_t)gnode * 128 + hu) = make_float2(h0, h1);
            if (hu < 64) {
                *(float2*)(g_c + (size_t)gnode * 64 + hu) = make_float2(c0, c1);
                __nv_bfloat16 hh0, hl0, hh1, hl1;
                split2(h0, hh0, hl0);
                split2(h1, hh1, hl1);
                __nv_bfloat162 hp = {hh0, hh1}, lp = {hl0, hl1};
                *(uint32_t*)(g_hh + (size_t)gnode * 64 + hu) = *(uint32_t*)&hp;
                *(uint32_t*)(g_hl + (size_t)gnode * 64 + hu) = *(uint32_t*)&lp;
            }
        }
    }
}

// =====================================================================
// Small-level SIMT kernel: 8 nodes per 256-thread block.
// =====================================================================
__global__ __launch_bounds__(256, 4)
void lstm_small_kernel(const float* __restrict__ x,
                       const float* __restrict__ Wih,
                       const float* __restrict__ Whh,
                       const float* __restrict__ bih,
                       const float* __restrict__ bhh,
                       float* __restrict__ out,
                       int start, int count, int isLeaf)
{
    __shared__ __align__(16) float As[8][196];
    __shared__ __align__(16) float Cs[8][128];
    __shared__ float bsm[512];

    const int t = threadIdx.x;
    const int tileBase = blockIdx.x * 8;

    for (int i = t; i < 512; i += 256) bsm[i] = bih[i] + bhh[i];

    for (int q = t; q < 384; q += 256) {
        int node = q / 48, c4 = q - node * 48, col = c4 * 4;
        float4 v = make_float4(0.f, 0.f, 0.f, 0.f);
        int nodeIdx = tileBase + node;
        if (nodeIdx < count) {
            int gnode = start + nodeIdx;
            if (col < 64) {
                v = *(const float4*)(x + (size_t)gnode * 64 + col);
            } else if (!isLeaf) {
                int child = (col < 128) ? (2 * gnode + 1) : (2 * gnode + 2);
                int cc    = (col < 128) ? (col - 64) : (col - 128);
                v = *(const float4*)(out + (size_t)child * 128 + cc);
            }
        }
        *(float4*)&As[node][col] = v;
    }
    {
        int node = t / 32, col = (t & 31) * 4;
        float4 v = make_float4(0.f, 0.f, 0.f, 0.f);
        int nodeIdx = tileBase + node;
        if (nodeIdx < count && !isLeaf) {
            int gnode = start + nodeIdx;
            int child = (col < 64) ? (2 * gnode + 1) : (2 * gnode + 2);
            int cc    = (col < 64) ? col : (col - 64);
            v = *(const float4*)&g_c[(size_t)child * 64 + cc];
        }
        *(float4*)&Cs[node][col] = v;
    }
    __syncthreads();

    const int hu = t & 127;
    const int np = t >> 7;
    float acc[4][4];
    #pragma unroll
    for (int n = 0; n < 4; ++n)
        #pragma unroll
        for (int g = 0; g < 4; ++g)
            acc[n][g] = bsm[hu + g * 128];

    for (int kc = 0; kc < 48; ++kc) {
        const int k0 = kc * 4;
        float4 w[4];
        #pragma unroll
        for (int g = 0; g < 4; ++g) {
            int grow = hu + g * 128;
            w[g] = (k0 < 64)
                 ? *(const float4*)(Wih + (size_t)grow * 64 + k0)
                 : *(const float4*)(Whh + (size_t)grow * 128 + (k0 - 64));
        }
        #pragma unroll
        for (int n = 0; n < 4; ++n) {
            float4 a = *(const float4*)&As[np + 2 * n][k0];
            #pragma unroll
            for (int g = 0; g < 4; ++g)
                acc[n][g] += a.x * w[g].x + a.y * w[g].y + a.z * w[g].z + a.w * w[g].w;
        }
    }

    #pragma unroll
    for (int n = 0; n < 4; ++n) {
        int nn = np + 2 * n;
        int nodeIdx = tileBase + nn;
        if (nodeIdx < count) {
            int gnode = start + nodeIdx;
            float cp = Cs[nn][hu];
            float c = sigf(acc[n][1]) * cp + sigf(acc[n][0]) * tanha(acc[n][2]);
            float h = sigf(acc[n][3]) * tanha(c);
            out[(size_t)gnode * 128 + hu] = h;
            if (hu < 64) g_c[(size_t)gnode * 64 + hu] = c;
        }
    }
}

extern "C" void kernel_launch(void* const* d_in, const int* in_sizes, int n_in,
                              void* d_out, int out_size)
{
    const float* x   = (const float*)d_in[0];   // [262143, 64]
    const float* Wih = (const float*)d_in[1];   // [512, 64]
    const float* Whh = (const float*)d_in[2];   // [512, 128]
    const float* bih = (const float*)d_in[3];   // [512]
    const float* bhh = (const float*)d_in[4];   // [512]
    float* out = (float*)d_out;                 // [262143, 128]

    static bool attr_done = false;
    if (!attr_done) {
        cudaFuncSetAttribute(lstm_tc_kernel,
                             cudaFuncAttributeMaxDynamicSharedMemorySize, SMEM_TC);
        attr_done = true;
    }

    prep_kernel<<<96, 256>>>(Wih, Whh, bih, bhh);

    for (int lvl = LEVELS - 1; lvl >= 0; --lvl) {
        int start = (1 << lvl) - 1;
        int count = 1 << lvl;
        int isLeaf = (lvl == LEVELS - 1);
        if (count >= 1024) {
            lstm_tc_kernel<<<count / 64, 256, SMEM_TC>>>(x, out, start, isLeaf);
        } else {
            lstm_small_kernel<<<(count + 7) / 8, 256>>>(
                x, Wih, Whh, bih, bhh, out, start, count, isLeaf);
        }
    }
}